// round 14
// baseline (speedup 1.0000x reference)
#include <cuda_runtime.h>
#include <cuda_bf16.h>
#include <stdint.h>

#define NN 100000
#define NE 1600000
#define SCAN_B 1024
#define NB ((NN + SCAN_B - 1) / SCAN_B)   // 98

#define B1U 68
#define B2U 68

// ---------------- scratch (device globals) ---------------------------------
__device__ int   g_is64;
__device__ int   g_cnt[NN];
__device__ int   g_rptr[NN + 1];
__device__ int   g_woff[NN];
__device__ int   g_bsum[NB];
__device__ int   g_col[NE];
__device__ __align__(16) float    g_z1[NN * 64];
__device__ __align__(16) float    g_r1[NN * 64];
__device__ __align__(16) uint32_t g_B1h[256 * B1U];
__device__ __align__(16) uint32_t g_B1l[256 * B1U];
__device__ __align__(16) uint32_t g_B2h[128 * B2U];
__device__ __align__(16) uint32_t g_B2l[128 * B2U];

// ---------------- helpers --------------------------------------------------
__device__ __forceinline__ uint32_t sptr(const void* p) {
    uint32_t a;
    asm("{ .reg .u64 t; cvta.to.shared.u64 t, %1; cvt.u32.u64 %0, t; }"
        : "=r"(a) : "l"(p));
    return a;
}

#define LDSM_X4(r0,r1,r2,r3,addr) \
    asm volatile("ldmatrix.sync.aligned.m8n8.x4.shared.b16 {%0,%1,%2,%3}, [%4];" \
        : "=r"(r0),"=r"(r1),"=r"(r2),"=r"(r3) : "r"(addr))

#define LDSM_X4_T(r0,r1,r2,r3,addr) \
    asm volatile("ldmatrix.sync.aligned.m8n8.x4.trans.shared.b16 {%0,%1,%2,%3}, [%4];" \
        : "=r"(r0),"=r"(r1),"=r"(r2),"=r"(r3) : "r"(addr))

#define MMA16816(c, a0,a1,a2,a3, b0,b1) \
    asm volatile("mma.sync.aligned.m16n8k16.row.col.f32.bf16.bf16.f32 " \
        "{%0,%1,%2,%3},{%4,%5,%6,%7},{%8,%9},{%0,%1,%2,%3};" \
        : "+f"((c)[0]),"+f"((c)[1]),"+f"((c)[2]),"+f"((c)[3]) \
        : "r"(a0),"r"(a1),"r"(a2),"r"(a3),"r"(b0),"r"(b1))

__device__ __forceinline__ void split2(float f0, float f1, uint32_t& hi, uint32_t& lo) {
    __nv_bfloat162 h, l;
    h.x = __float2bfloat16(f0);
    h.y = __float2bfloat16(f1);
    l.x = __float2bfloat16(f0 - __bfloat162float(h.x));
    l.y = __float2bfloat16(f1 - __bfloat162float(h.y));
    hi = *reinterpret_cast<uint32_t*>(&h);
    lo = *reinterpret_cast<uint32_t*>(&l);
}

__device__ __forceinline__ int edge_at(const void* ei, int idx) {
    return g_is64 ? (int)((const long long*)ei)[idx] : ((const int*)ei)[idx];
}

// ---------------- CSR build ----------------
// zero counts; block 0 additionally detects edge_index dtype
__global__ void k_zero(const int* __restrict__ ei32, int n) {
    int i = blockIdx.x * blockDim.x + threadIdx.x;
    if (i < n) g_cnt[i] = 0;
    if (blockIdx.x == 0) {
        __shared__ int nz;
        if (threadIdx.x == 0) nz = 0;
        __syncthreads();
        int v = 0;
        for (int j = threadIdx.x; j < 1024; j += 256) v |= ei32[2 * j + 1];
        if (v) atomicOr(&nz, 1);
        __syncthreads();
        if (threadIdx.x == 0) g_is64 = (nz == 0) ? 1 : 0;
    }
}

__global__ void k_hist(const void* __restrict__ ei, int E) {
    int e = blockIdx.x * blockDim.x + threadIdx.x;
    if (e < E) {
        int d = edge_at(ei, E + e);
        if ((unsigned)d < (unsigned)NN) atomicAdd(&g_cnt[d], 1);
    }
}

__global__ void k_scan_blocks(int n) {
    __shared__ int wsum[32];
    int tid  = threadIdx.x;
    int lane = tid & 31, wid = tid >> 5;
    int i = blockIdx.x * SCAN_B + tid;
    int v = (i < n) ? g_cnt[i] : 0;
    int x = v;
    #pragma unroll
    for (int d = 1; d < 32; d <<= 1) {
        int t = __shfl_up_sync(0xffffffffu, x, d);
        if (lane >= d) x += t;
    }
    if (lane == 31) wsum[wid] = x;
    __syncthreads();
    if (wid == 0) {
        int s = wsum[lane];
        #pragma unroll
        for (int d = 1; d < 32; d <<= 1) {
            int t = __shfl_up_sync(0xffffffffu, s, d);
            if (lane >= d) s += t;
        }
        wsum[lane] = s;
    }
    __syncthreads();
    int woffs = (wid > 0) ? wsum[wid - 1] : 0;
    if (i < n) g_rptr[i] = woffs + x - v;
    if (tid == SCAN_B - 1) g_bsum[blockIdx.x] = wsum[31];
}

// add block offsets; each block redundantly scans the 98-entry bsum in smem
__global__ void k_add_off(int n, int E, int nb) {
    __shared__ int pre[NB];
    int tid = threadIdx.x;
    if (tid < nb) pre[tid] = g_bsum[tid];
    __syncthreads();
    if (tid == 0) {
        int a = 0;
        for (int i = 0; i < nb; i++) { int t = pre[i]; pre[i] = a; a += t; }
    }
    __syncthreads();
    int i = blockIdx.x * SCAN_B + tid;
    if (i < n) {
        int v = g_rptr[i] + pre[blockIdx.x];
        g_rptr[i] = v;
        g_woff[i] = v;
    }
    if (i == 0) g_rptr[n] = E;
}

__global__ void k_scatter(const void* __restrict__ ei, int E) {
    int e = blockIdx.x * blockDim.x + threadIdx.x;
    if (e < E) {
        int s = edge_at(ei, e);
        int d = edge_at(ei, E + e);
        if ((unsigned)s < (unsigned)NN && (unsigned)d < (unsigned)NN) {
            int p = atomicAdd(&g_woff[d], 1);
            if ((unsigned)p < (unsigned)NE) g_col[p] = s;
        }
    }
}

// ---------------- weight packing: fp32 -> bf16 hi/lo, padded rows ----------
__global__ void k_pack(const float* __restrict__ Wl0, const float* __restrict__ Wr0,
                       const float* __restrict__ Wl1, const float* __restrict__ Wr1) {
    int i = blockIdx.x * blockDim.x + threadIdx.x;
    if (i < 256 * B1U) {
        int k = i / B1U, c = i % B1U;
        float f0 = 0.f, f1 = 0.f;
        if (c < 64) {
            const float* W = (k < 128) ? Wl0 : Wr0;
            int kk = k & 127;
            f0 = W[kk * 128 + 2 * c];
            f1 = W[kk * 128 + 2 * c + 1];
        }
        uint32_t hi, lo;
        split2(f0, f1, hi, lo);
        g_B1h[i] = hi; g_B1l[i] = lo;
    }
    if (i < 128 * B2U) {
        int k = i / B2U, c = i % B2U;
        float f0 = 0.f, f1 = 0.f;
        if (c < 32) {
            f0 = Wl1[k * 64 + 2 * c];
            f1 = Wl1[k * 64 + 2 * c + 1];
        } else if (c < 64) {
            int cc = c - 32;
            f0 = Wr1[k * 64 + 2 * cc];
            f1 = Wr1[k * 64 + 2 * cc + 1];
        }
        uint32_t hi, lo;
        split2(f0, f1, hi, lo);
        g_B2h[i] = hi; g_B2l[i] = lo;
    }
}

// ---------------- mega kernel: gather + GEMM1(+relu) + GEMM2 ---------------
// AggH/AggL: 64 rows x 64 u32 (bf16 pairs), stride 68 u32 = 272 B (16B-aligned,
// bank-rotating). Gather writes it; GEMM1 k<128 reads it via ldmatrix; h is
// split back into it; GEMM2 reads it. x-half A fragments come straight from
// global (each lane loads its own-fragment float2s; rows are L1-resident).
__global__ void __launch_bounds__(256) k_layer1(
    const float* __restrict__ x,
    const float* __restrict__ bias,
    int M)
{
    __shared__ __align__(16) uint32_t AggH[64 * 68];
    __shared__ __align__(16) uint32_t AggL[64 * 68];
    __shared__ __align__(16) uint32_t BsH[16 * B1U];
    __shared__ __align__(16) uint32_t BsL[16 * B1U];

    int tid  = threadIdx.x;
    int lane = tid & 31, w = tid >> 5;
    int tile0 = blockIdx.x * 64;

    // -------- Phase A: gather-mean of x, split to bf16 hi/lo ---------------
    #pragma unroll 1
    for (int u = 0; u < 8; u++) {
        int r = w * 8 + u;
        int node = tile0 + r;
        float4 acc4 = make_float4(0.f, 0.f, 0.f, 0.f);
        if (node < M) {
            int rs = g_rptr[node], re = g_rptr[node + 1];
            int j = rs;
            for (; j + 4 <= re; j += 4) {
                int s0 = g_col[j], s1 = g_col[j+1], s2 = g_col[j+2], s3 = g_col[j+3];
                float4 v0 = *(const float4*)&x[s0 * 128 + lane * 4];
                float4 v1 = *(const float4*)&x[s1 * 128 + lane * 4];
                float4 v2 = *(const float4*)&x[s2 * 128 + lane * 4];
                float4 v3 = *(const float4*)&x[s3 * 128 + lane * 4];
                acc4.x += v0.x + v1.x + v2.x + v3.x;
                acc4.y += v0.y + v1.y + v2.y + v3.y;
                acc4.z += v0.z + v1.z + v2.z + v3.z;
                acc4.w += v0.w + v1.w + v2.w + v3.w;
            }
            for (; j < re; j++) {
                int s = g_col[j];
                float4 v = *(const float4*)&x[s * 128 + lane * 4];
                acc4.x += v.x; acc4.y += v.y; acc4.z += v.z; acc4.w += v.w;
            }
            int deg = re - rs;
            float inv = 1.0f / (float)(deg > 1 ? deg : 1);
            acc4.x *= inv; acc4.y *= inv; acc4.z *= inv; acc4.w *= inv;
        }
        uint32_t h0, l0, h1, l1;
        split2(acc4.x, acc4.y, h0, l0);
        split2(acc4.z, acc4.w, h1, l1);
        uint2 ph; ph.x = h0; ph.y = h1;
        uint2 pl; pl.x = l0; pl.y = l1;
        *(uint2*)&AggH[r * 68 + lane * 2] = ph;
        *(uint2*)&AggL[r * 68 + lane * 2] = pl;
    }

    // -------- per-warp MMA geometry ----------------------------------------
    int wr = (w & 3) * 16;
    int wc = (w >> 2) * 64;

    uint32_t aBaseH = sptr(AggH) + (wr + (lane & 15)) * 272 + ((lane >> 4) << 4);
    uint32_t aBaseL = sptr(AggL) + (wr + (lane & 15)) * 272 + ((lane >> 4) << 4);
    uint32_t bBase  = (lane & 15) * (B1U * 4) + (wc + ((lane >> 4) << 3)) * 2;
    uint32_t bAddrH = sptr(BsH) + bBase;
    uint32_t bAddrL = sptr(BsL) + bBase;

    int g  = lane >> 2;
    int t2 = (lane & 3) * 2;
    int r0   = wr + g;
    int col0 = wc + t2;
    int gm0  = tile0 + r0;
    int gm1  = gm0 + 8;

    // -------- Phase B: GEMM1 [Agg | x] (K=256) @ B1 ------------------------
    float acc[8][4];
    #pragma unroll
    for (int t = 0; t < 8; t++) {
        acc[t][0] = 0.f; acc[t][1] = 0.f; acc[t][2] = 0.f; acc[t][3] = 0.f;
    }

    // k-chunks 0..7: A = AggBf (smem, stable)
    for (int kc = 0; kc < 128; kc += 16) {
        __syncthreads();                       // gather done (kc=0) / Bs consumed
        uint32_t ah0, ah1, ah2, ah3, al0, al1, al2, al3;
        LDSM_X4(ah0, ah1, ah2, ah3, aBaseH + kc * 2);   // overlaps Bs fill
        LDSM_X4(al0, al1, al2, al3, aBaseL + kc * 2);
        {
            const uint4* s4h = (const uint4*)(g_B1h + kc * B1U);
            const uint4* s4l = (const uint4*)(g_B1l + kc * B1U);
            #pragma unroll
            for (int i = tid; i < 16 * B1U / 4; i += 256) {
                ((uint4*)BsH)[i] = s4h[i];
                ((uint4*)BsL)[i] = s4l[i];
            }
        }
        __syncthreads();
        #pragma unroll
        for (int p = 0; p < 4; p++) {
            uint32_t bh0, bh1, bh2, bh3, bl0, bl1, bl2, bl3;
            LDSM_X4_T(bh0, bh1, bh2, bh3, bAddrH + p * 32);
            LDSM_X4_T(bl0, bl1, bl2, bl3, bAddrL + p * 32);
            MMA16816(acc[2*p],   ah0, ah1, ah2, ah3, bh0, bh1);
            MMA16816(acc[2*p],   ah0, ah1, ah2, ah3, bl0, bl1);
            MMA16816(acc[2*p],   al0, al1, al2, al3, bh0, bh1);
            MMA16816(acc[2*p+1], ah0, ah1, ah2, ah3, bh2, bh3);
            MMA16816(acc[2*p+1], ah0, ah1, ah2, ah3, bl2, bl3);
            MMA16816(acc[2*p+1], al0, al1, al2, al3, bh2, bh3);
        }
    }

    // k-chunks 8..15: A fragments straight from global x (own rows)
    for (int kc = 128; kc < 256; kc += 16) {
        int kb = kc - 128;
        float2 p0 = make_float2(0.f, 0.f), p1 = p0, p2 = p0, p3 = p0;
        {
            int ga = tile0 + wr + g, gb = ga + 8;
            if (ga < M) {
                p0 = *(const float2*)&x[ga * 128 + kb + t2];
                p2 = *(const float2*)&x[ga * 128 + kb + 8 + t2];
            }
            if (gb < M) {
                p1 = *(const float2*)&x[gb * 128 + kb + t2];
                p3 = *(const float2*)&x[gb * 128 + kb + 8 + t2];
            }
        }
        __syncthreads();
        {
            const uint4* s4h = (const uint4*)(g_B1h + kc * B1U);
            const uint4* s4l = (const uint4*)(g_B1l + kc * B1U);
            #pragma unroll
            for (int i = tid; i < 16 * B1U / 4; i += 256) {
                ((uint4*)BsH)[i] = s4h[i];
                ((uint4*)BsL)[i] = s4l[i];
            }
        }
        uint32_t ah0, ah1, ah2, ah3, al0, al1, al2, al3;
        split2(p0.x, p0.y, ah0, al0);
        split2(p1.x, p1.y, ah1, al1);
        split2(p2.x, p2.y, ah2, al2);
        split2(p3.x, p3.y, ah3, al3);
        __syncthreads();
        #pragma unroll
        for (int p = 0; p < 4; p++) {
            uint32_t bh0, bh1, bh2, bh3, bl0, bl1, bl2, bl3;
            LDSM_X4_T(bh0, bh1, bh2, bh3, bAddrH + p * 32);
            LDSM_X4_T(bl0, bl1, bl2, bl3, bAddrL + p * 32);
            MMA16816(acc[2*p],   ah0, ah1, ah2, ah3, bh0, bh1);
            MMA16816(acc[2*p],   ah0, ah1, ah2, ah3, bl0, bl1);
            MMA16816(acc[2*p],   al0, al1, al2, al3, bh0, bh1);
            MMA16816(acc[2*p+1], ah0, ah1, ah2, ah3, bh2, bh3);
            MMA16816(acc[2*p+1], ah0, ah1, ah2, ah3, bl2, bl3);
            MMA16816(acc[2*p+1], al0, al1, al2, al3, bh2, bh3);
        }
    }

    __syncthreads();   // all chunk-15 Bs/Agg reads done before h overwrites Agg

    // -------- h = relu(acc + bias) -> AggBf (bf16 hi/lo) --------------------
    #pragma unroll
    for (int nt = 0; nt < 8; nt++) {
        int col = col0 + nt * 8;
        float b0 = bias[col], b1 = bias[col + 1];
        float h00 = acc[nt][0] + b0, h01 = acc[nt][1] + b1;
        float h10 = acc[nt][2] + b0, h11 = acc[nt][3] + b1;
        h00 = h00 > 0.f ? h00 : 0.f;  h01 = h01 > 0.f ? h01 : 0.f;
        h10 = h10 > 0.f ? h10 : 0.f;  h11 = h11 > 0.f ? h11 : 0.f;
        uint32_t hh, hl;
        split2(h00, h01, hh, hl);
        AggH[r0 * 68 + (col >> 1)] = hh;
        AggL[r0 * 68 + (col >> 1)] = hl;
        split2(h10, h11, hh, hl);
        AggH[(r0 + 8) * 68 + (col >> 1)] = hh;
        AggL[(r0 + 8) * 68 + (col >> 1)] = hl;
    }

    // -------- Phase C: GEMM2 h (K=128, smem) @ B2 -> z1 | r1 ---------------
    float acc2[8][4];
    #pragma unroll
    for (int t = 0; t < 8; t++) {
        acc2[t][0] = 0.f; acc2[t][1] = 0.f; acc2[t][2] = 0.f; acc2[t][3] = 0.f;
    }

    for (int kc = 0; kc < 128; kc += 16) {
        __syncthreads();                      // h writes done (kc=0) / Bs consumed
        uint32_t ah0, ah1, ah2, ah3, al0, al1, al2, al3;
        LDSM_X4(ah0, ah1, ah2, ah3, aBaseH + kc * 2);
        LDSM_X4(al0, al1, al2, al3, aBaseL + kc * 2);
        {
            const uint4* s4h = (const uint4*)(g_B2h + kc * B2U);
            const uint4* s4l = (const uint4*)(g_B2l + kc * B2U);
            #pragma unroll
            for (int i = tid; i < 16 * B2U / 4; i += 256) {
                ((uint4*)BsH)[i] = s4h[i];
                ((uint4*)BsL)[i] = s4l[i];
            }
        }
        __syncthreads();
        #pragma unroll
        for (int p = 0; p < 4; p++) {
            uint32_t bh0, bh1, bh2, bh3, bl0, bl1, bl2, bl3;
            LDSM_X4_T(bh0, bh1, bh2, bh3, bAddrH + p * 32);
            LDSM_X4_T(bl0, bl1, bl2, bl3, bAddrL + p * 32);
            MMA16816(acc2[2*p],   ah0, ah1, ah2, ah3, bh0, bh1);
            MMA16816(acc2[2*p],   ah0, ah1, ah2, ah3, bl0, bl1);
            MMA16816(acc2[2*p],   al0, al1, al2, al3, bh0, bh1);
            MMA16816(acc2[2*p+1], ah0, ah1, ah2, ah3, bh2, bh3);
            MMA16816(acc2[2*p+1], ah0, ah1, ah2, ah3, bl2, bl3);
            MMA16816(acc2[2*p+1], al0, al1, al2, al3, bh2, bh3);
        }
    }

    // -------- epilogue: z1 | r1 --------
    #pragma unroll
    for (int nt = 0; nt < 8; nt++) {
        int col = col0 + nt * 8;
        float* dst = (col < 64) ? g_z1 : g_r1;
        int c = col & 63;
        if (gm0 < M) {
            float2 o; o.x = acc2[nt][0]; o.y = acc2[nt][1];
            *(float2*)&dst[gm0 * 64 + c] = o;
        }
        if (gm1 < M) {
            float2 o; o.x = acc2[nt][2]; o.y = acc2[nt][3];
            *(float2*)&dst[gm1 * 64 + c] = o;
        }
    }
}

// ---------------- final: out = mean_agg(z1) + bl1 + r1 ---------------------
__global__ void k_out(const float* __restrict__ bias, float* __restrict__ out, int n) {
    int warp = (blockIdx.x * blockDim.x + threadIdx.x) >> 5;
    int lane = threadIdx.x & 31;
    if (warp >= n) return;
    int rs = g_rptr[warp], re = g_rptr[warp + 1];
    int d0 = lane * 2;
    float2 acc = make_float2(0.f, 0.f);
    int j = rs;
    for (; j + 4 <= re; j += 4) {
        int s0 = g_col[j], s1 = g_col[j + 1], s2 = g_col[j + 2], s3 = g_col[j + 3];
        float2 v0 = *(const float2*)&g_z1[s0 * 64 + d0];
        float2 v1 = *(const float2*)&g_z1[s1 * 64 + d0];
        float2 v2 = *(const float2*)&g_z1[s2 * 64 + d0];
        float2 v3 = *(const float2*)&g_z1[s3 * 64 + d0];
        acc.x += v0.x + v1.x + v2.x + v3.x;
        acc.y += v0.y + v1.y + v2.y + v3.y;
    }
    for (; j < re; j++) {
        int s = g_col[j];
        float2 v = *(const float2*)&g_z1[s * 64 + d0];
        acc.x += v.x; acc.y += v.y;
    }
    int deg = re - rs;
    float inv = 1.0f / (float)(deg > 1 ? deg : 1);
    float2 r = *(const float2*)&g_r1[warp * 64 + d0];
    float2 o;
    o.x = acc.x * inv + bias[d0]     + r.x;
    o.y = acc.y * inv + bias[d0 + 1] + r.y;
    *(float2*)&out[warp * 64 + d0] = o;
}

// ---------------- launch (kernel launches ONLY) ----------------------------
extern "C" void kernel_launch(void* const* d_in, const int* in_sizes, int n_in,
                              void* d_out, int out_size) {
    const float* x   = (const float*)d_in[0];
    const void*  ei  = d_in[1];
    const float* Wl0 = (const float*)d_in[2];
    const float* bl0 = (const float*)d_in[3];
    const float* Wr0 = (const float*)d_in[4];
    const float* Wl1 = (const float*)d_in[5];
    const float* bl1 = (const float*)d_in[6];
    const float* Wr1 = (const float*)d_in[7];
    float* out = (float*)d_out;

    int M = in_sizes[0] / 128;      // 100000
    int E = in_sizes[1] / 2;        // 1600000

    k_zero<<<(M + 255) / 256, 256>>>((const int*)ei, M);
    k_hist<<<(E + 255) / 256, 256>>>(ei, E);
    k_scan_blocks<<<NB, SCAN_B>>>(M);
    k_add_off<<<NB, SCAN_B>>>(M, E, NB);
    k_scatter<<<(E + 255) / 256, 256>>>(ei, E);
    k_pack<<<(256 * B1U + 255) / 256, 256>>>(Wl0, Wr0, Wl1, Wr1);

    int tiles = (M + 63) / 64;
    k_layer1<<<tiles, 256>>>(x, bl0, M);
    k_out<<<(M + 7) / 8, 256>>>(bl1, out, M);
}

// round 16
// speedup vs baseline: 1.1434x; 1.1434x over previous
#include <cuda_runtime.h>
#include <cuda_bf16.h>
#include <stdint.h>

#define NN 100000
#define NE 1600000
#define SCAN_B 1024
#define NB ((NN + SCAN_B - 1) / SCAN_B)   // 98

#define B1U 68
#define B2U 68
#define BCH4 (16 * B1U / 4)   // 272 uint4 per B chunk buffer

// ---------------- scratch (device globals) ---------------------------------
__device__ int   g_is64;
__device__ int   g_cnt[NN];
__device__ int   g_rptr[NN + 1];
__device__ int   g_woff[NN];
__device__ int   g_bsum[NB];
__device__ int   g_col[NE];
__device__ __align__(16) float    g_z1[NN * 64];
__device__ __align__(16) float    g_r1[NN * 64];
__device__ __align__(16) uint32_t g_B1h[256 * B1U];
__device__ __align__(16) uint32_t g_B1l[256 * B1U];
__device__ __align__(16) uint32_t g_B2h[128 * B2U];
__device__ __align__(16) uint32_t g_B2l[128 * B2U];

// ---------------- helpers --------------------------------------------------
__device__ __forceinline__ uint32_t sptr(const void* p) {
    uint32_t a;
    asm("{ .reg .u64 t; cvta.to.shared.u64 t, %1; cvt.u32.u64 %0, t; }"
        : "=r"(a) : "l"(p));
    return a;
}

#define LDSM_X4(r0,r1,r2,r3,addr) \
    asm volatile("ldmatrix.sync.aligned.m8n8.x4.shared.b16 {%0,%1,%2,%3}, [%4];" \
        : "=r"(r0),"=r"(r1),"=r"(r2),"=r"(r3) : "r"(addr))

#define LDSM_X4_T(r0,r1,r2,r3,addr) \
    asm volatile("ldmatrix.sync.aligned.m8n8.x4.trans.shared.b16 {%0,%1,%2,%3}, [%4];" \
        : "=r"(r0),"=r"(r1),"=r"(r2),"=r"(r3) : "r"(addr))

#define MMA16816(c, a0,a1,a2,a3, b0,b1) \
    asm volatile("mma.sync.aligned.m16n8k16.row.col.f32.bf16.bf16.f32 " \
        "{%0,%1,%2,%3},{%4,%5,%6,%7},{%8,%9},{%0,%1,%2,%3};" \
        : "+f"((c)[0]),"+f"((c)[1]),"+f"((c)[2]),"+f"((c)[3]) \
        : "r"(a0),"r"(a1),"r"(a2),"r"(a3),"r"(b0),"r"(b1))

__device__ __forceinline__ void split2(float f0, float f1, uint32_t& hi, uint32_t& lo) {
    __nv_bfloat162 h, l;
    h.x = __float2bfloat16(f0);
    h.y = __float2bfloat16(f1);
    l.x = __float2bfloat16(f0 - __bfloat162float(h.x));
    l.y = __float2bfloat16(f1 - __bfloat162float(h.y));
    hi = *reinterpret_cast<uint32_t*>(&h);
    lo = *reinterpret_cast<uint32_t*>(&l);
}

__device__ __forceinline__ int edge_at(const void* ei, int idx) {
    return g_is64 ? (int)((const long long*)ei)[idx] : ((const int*)ei)[idx];
}

// ---------------- CSR build ----------------
__global__ void k_zero(const int* __restrict__ ei32, int n) {
    int i = blockIdx.x * blockDim.x + threadIdx.x;
    if (i < n) g_cnt[i] = 0;
    if (blockIdx.x == 0) {
        __shared__ int nz;
        if (threadIdx.x == 0) nz = 0;
        __syncthreads();
        int v = 0;
        for (int j = threadIdx.x; j < 1024; j += 256) v |= ei32[2 * j + 1];
        if (v) atomicOr(&nz, 1);
        __syncthreads();
        if (threadIdx.x == 0) g_is64 = (nz == 0) ? 1 : 0;
    }
}

__global__ void k_hist(const void* __restrict__ ei, int E) {
    int e = blockIdx.x * blockDim.x + threadIdx.x;
    if (e < E) {
        int d = edge_at(ei, E + e);
        if ((unsigned)d < (unsigned)NN) atomicAdd(&g_cnt[d], 1);
    }
}

__global__ void k_scan_blocks(int n) {
    __shared__ int wsum[32];
    int tid  = threadIdx.x;
    int lane = tid & 31, wid = tid >> 5;
    int i = blockIdx.x * SCAN_B + tid;
    int v = (i < n) ? g_cnt[i] : 0;
    int x = v;
    #pragma unroll
    for (int d = 1; d < 32; d <<= 1) {
        int t = __shfl_up_sync(0xffffffffu, x, d);
        if (lane >= d) x += t;
    }
    if (lane == 31) wsum[wid] = x;
    __syncthreads();
    if (wid == 0) {
        int s = wsum[lane];
        #pragma unroll
        for (int d = 1; d < 32; d <<= 1) {
            int t = __shfl_up_sync(0xffffffffu, s, d);
            if (lane >= d) s += t;
        }
        wsum[lane] = s;
    }
    __syncthreads();
    int woffs = (wid > 0) ? wsum[wid - 1] : 0;
    if (i < n) g_rptr[i] = woffs + x - v;
    if (tid == SCAN_B - 1) g_bsum[blockIdx.x] = wsum[31];
}

__global__ void k_add_off(int n, int E, int nb) {
    __shared__ int pre[NB];
    int tid = threadIdx.x;
    if (tid < nb) pre[tid] = g_bsum[tid];
    __syncthreads();
    if (tid == 0) {
        int a = 0;
        for (int i = 0; i < nb; i++) { int t = pre[i]; pre[i] = a; a += t; }
    }
    __syncthreads();
    int i = blockIdx.x * SCAN_B + tid;
    if (i < n) {
        int v = g_rptr[i] + pre[blockIdx.x];
        g_rptr[i] = v;
        g_woff[i] = v;
    }
    if (i == 0) g_rptr[n] = E;
}

__global__ void k_scatter(const void* __restrict__ ei, int E) {
    int e = blockIdx.x * blockDim.x + threadIdx.x;
    if (e < E) {
        int s = edge_at(ei, e);
        int d = edge_at(ei, E + e);
        if ((unsigned)s < (unsigned)NN && (unsigned)d < (unsigned)NN) {
            int p = atomicAdd(&g_woff[d], 1);
            if ((unsigned)p < (unsigned)NE) g_col[p] = s;
        }
    }
}

// ---------------- weight packing: fp32 -> bf16 hi/lo, padded rows ----------
__global__ void k_pack(const float* __restrict__ Wl0, const float* __restrict__ Wr0,
                       const float* __restrict__ Wl1, const float* __restrict__ Wr1) {
    int i = blockIdx.x * blockDim.x + threadIdx.x;
    if (i < 256 * B1U) {
        int k = i / B1U, c = i % B1U;
        float f0 = 0.f, f1 = 0.f;
        if (c < 64) {
            const float* W = (k < 128) ? Wl0 : Wr0;
            int kk = k & 127;
            f0 = W[kk * 128 + 2 * c];
            f1 = W[kk * 128 + 2 * c + 1];
        }
        uint32_t hi, lo;
        split2(f0, f1, hi, lo);
        g_B1h[i] = hi; g_B1l[i] = lo;
    }
    if (i < 128 * B2U) {
        int k = i / B2U, c = i % B2U;
        float f0 = 0.f, f1 = 0.f;
        if (c < 32) {
            f0 = Wl1[k * 64 + 2 * c];
            f1 = Wl1[k * 64 + 2 * c + 1];
        } else if (c < 64) {
            int cc = c - 32;
            f0 = Wr1[k * 64 + 2 * cc];
            f1 = Wr1[k * 64 + 2 * cc + 1];
        }
        uint32_t hi, lo;
        split2(f0, f1, hi, lo);
        g_B2h[i] = hi; g_B2l[i] = lo;
    }
}

// ---------------- mega kernel: gather + GEMM1(+relu) + GEMM2 ---------------
// R13 structure (fp32 Agg + per-chunk bf16 staging) with register-prefetch
// pipelining: chunk kc+1's B-weights (and x-half A float4) are LDG'd into
// registers DURING chunk kc's MMA, so L2 latency overlaps tensor work.
__global__ void __launch_bounds__(256) k_layer1(
    const float* __restrict__ x,
    const float* __restrict__ bias,
    int M)
{
    __shared__ float    Agg[64][132];
    __shared__ __align__(16) uint32_t Ahu[64 * 12];
    __shared__ __align__(16) uint32_t Alu[64 * 12];
    __shared__ __align__(16) uint32_t BsH[16 * B1U];
    __shared__ __align__(16) uint32_t BsL[16 * B1U];

    int tid  = threadIdx.x;
    int lane = tid & 31, w = tid >> 5;
    int tile0 = blockIdx.x * 64;

    // -------- Phase A: gather-mean of x into Agg (fp32) --------
    #pragma unroll 1
    for (int u = 0; u < 8; u++) {
        int r = w * 8 + u;
        int node = tile0 + r;
        float4 acc4 = make_float4(0.f, 0.f, 0.f, 0.f);
        if (node < M) {
            int rs = g_rptr[node], re = g_rptr[node + 1];
            int j = rs;
            for (; j + 4 <= re; j += 4) {
                int s0 = g_col[j], s1 = g_col[j+1], s2 = g_col[j+2], s3 = g_col[j+3];
                float4 v0 = *(const float4*)&x[s0 * 128 + lane * 4];
                float4 v1 = *(const float4*)&x[s1 * 128 + lane * 4];
                float4 v2 = *(const float4*)&x[s2 * 128 + lane * 4];
                float4 v3 = *(const float4*)&x[s3 * 128 + lane * 4];
                acc4.x += v0.x + v1.x + v2.x + v3.x;
                acc4.y += v0.y + v1.y + v2.y + v3.y;
                acc4.z += v0.z + v1.z + v2.z + v3.z;
                acc4.w += v0.w + v1.w + v2.w + v3.w;
            }
            for (; j < re; j++) {
                int s = g_col[j];
                float4 v = *(const float4*)&x[s * 128 + lane * 4];
                acc4.x += v.x; acc4.y += v.y; acc4.z += v.z; acc4.w += v.w;
            }
            int deg = re - rs;
            float inv = 1.0f / (float)(deg > 1 ? deg : 1);
            acc4.x *= inv; acc4.y *= inv; acc4.z *= inv; acc4.w *= inv;
        }
        *(float4*)&Agg[r][lane * 4] = acc4;
    }

    // -------- per-warp MMA geometry --------
    int wr = (w & 3) * 16;
    int wc = (w >> 2) * 64;

    uint32_t aAddrH = sptr(Ahu) + (wr + (lane & 15)) * 48 + ((lane >> 4) << 4);
    uint32_t aAddrL = sptr(Alu) + (wr + (lane & 15)) * 48 + ((lane >> 4) << 4);
    uint32_t bBase  = (lane & 15) * (B1U * 4) + (wc + ((lane >> 4) << 3)) * 2;
    uint32_t bAddrH = sptr(BsH) + bBase;
    uint32_t bAddrL = sptr(BsL) + bBase;

    int arow = tid >> 2;
    int akp  = (tid & 3) * 4;
    int acol = arow * 12 + (tid & 3) * 2;

    int r0   = wr + (lane >> 2);
    int col0 = wc + (lane & 3) * 2;
    int gm0  = tile0 + r0;
    int gm1  = gm0 + 8;

    // prefetch registers
    uint4 pbH0, pbL0, pbH1, pbL1;
    float4 aPre = make_float4(0.f, 0.f, 0.f, 0.f);

    // prologue: prefetch B chunk 0 (independent of gather barrier)
    {
        const uint4* s4h = (const uint4*)(g_B1h);
        const uint4* s4l = (const uint4*)(g_B1l);
        pbH0 = s4h[tid]; pbL0 = s4l[tid];
        if (tid < BCH4 - 256) { pbH1 = s4h[256 + tid]; pbL1 = s4l[256 + tid]; }
    }
    __syncthreads();   // gather complete: Agg readable

    // -------- Phase B: GEMM1 [Agg | x] (K=256) @ B1 --------
    float acc[8][4];
    #pragma unroll
    for (int t = 0; t < 8; t++) {
        acc[t][0] = 0.f; acc[t][1] = 0.f; acc[t][2] = 0.f; acc[t][3] = 0.f;
    }

    #pragma unroll 1
    for (int c = 0; c < 16; c++) {
        int kc = c * 16;
        // store prefetched B to smem
        ((uint4*)BsH)[tid] = pbH0;
        ((uint4*)BsL)[tid] = pbL0;
        if (tid < BCH4 - 256) {
            ((uint4*)BsH)[256 + tid] = pbH1;
            ((uint4*)BsL)[256 + tid] = pbL1;
        }
        // stage A chunk: fp32 -> bf16 hi/lo
        {
            float4 v = (kc < 128) ? *(const float4*)&Agg[arow][kc + akp] : aPre;
            uint32_t h0, l0, h1, l1;
            split2(v.x, v.y, h0, l0);
            split2(v.z, v.w, h1, l1);
            Ahu[acol] = h0; Ahu[acol + 1] = h1;
            Alu[acol] = l0; Alu[acol + 1] = l1;
        }
        __syncthreads();
        // prefetch next chunk (overlaps MMA below)
        if (c < 15) {
            int nk = kc + 16;
            const uint4* s4h = (const uint4*)(g_B1h + nk * B1U);
            const uint4* s4l = (const uint4*)(g_B1l + nk * B1U);
            pbH0 = s4h[tid]; pbL0 = s4l[tid];
            if (tid < BCH4 - 256) { pbH1 = s4h[256 + tid]; pbL1 = s4l[256 + tid]; }
            if (nk >= 128) {
                int gr = tile0 + arow;
                aPre = make_float4(0.f, 0.f, 0.f, 0.f);
                if (gr < M) aPre = *(const float4*)&x[gr * 128 + (nk - 128) + akp];
            }
        }

        uint32_t ah0, ah1, ah2, ah3, al0, al1, al2, al3;
        LDSM_X4(ah0, ah1, ah2, ah3, aAddrH);
        LDSM_X4(al0, al1, al2, al3, aAddrL);

        #pragma unroll
        for (int p = 0; p < 4; p++) {
            uint32_t bh0, bh1, bh2, bh3, bl0, bl1, bl2, bl3;
            LDSM_X4_T(bh0, bh1, bh2, bh3, bAddrH + p * 32);
            LDSM_X4_T(bl0, bl1, bl2, bl3, bAddrL + p * 32);
            MMA16816(acc[2*p],   ah0, ah1, ah2, ah3, bh0, bh1);
            MMA16816(acc[2*p],   ah0, ah1, ah2, ah3, bl0, bl1);
            MMA16816(acc[2*p],   al0, al1, al2, al3, bh0, bh1);
            MMA16816(acc[2*p+1], ah0, ah1, ah2, ah3, bh2, bh3);
            MMA16816(acc[2*p+1], ah0, ah1, ah2, ah3, bl2, bl3);
            MMA16816(acc[2*p+1], al0, al1, al2, al3, bh2, bh3);
        }
        __syncthreads();
    }

    // -------- h = relu(acc + bias) -> Agg (fp32 smem) --------
    #pragma unroll
    for (int nt = 0; nt < 8; nt++) {
        int col = col0 + nt * 8;
        float b0 = bias[col], b1 = bias[col + 1];
        float2 o;
        o.x = acc[nt][0] + b0; o.y = acc[nt][1] + b1;
        o.x = o.x > 0.f ? o.x : 0.f;
        o.y = o.y > 0.f ? o.y : 0.f;
        *(float2*)&Agg[r0][col] = o;
        o.x = acc[nt][2] + b0; o.y = acc[nt][3] + b1;
        o.x = o.x > 0.f ? o.x : 0.f;
        o.y = o.y > 0.f ? o.y : 0.f;
        *(float2*)&Agg[r0 + 8][col] = o;
    }

    // reuse acc for GEMM2
    #pragma unroll
    for (int t = 0; t < 8; t++) {
        acc[t][0] = 0.f; acc[t][1] = 0.f; acc[t][2] = 0.f; acc[t][3] = 0.f;
    }
    // prefetch B2 chunk 0
    {
        const uint4* s4h = (const uint4*)(g_B2h);
        const uint4* s4l = (const uint4*)(g_B2l);
        pbH0 = s4h[tid]; pbL0 = s4l[tid];
        if (tid < BCH4 - 256) { pbH1 = s4h[256 + tid]; pbL1 = s4l[256 + tid]; }
    }
    __syncthreads();   // h writes visible to all warps

    // -------- Phase C: GEMM2 h (K=128, smem) @ B2 -> z1 | r1 ---------------
    #pragma unroll 1
    for (int c = 0; c < 8; c++) {
        int kc = c * 16;
        ((uint4*)BsH)[tid] = pbH0;
        ((uint4*)BsL)[tid] = pbL0;
        if (tid < BCH4 - 256) {
            ((uint4*)BsH)[256 + tid] = pbH1;
            ((uint4*)BsL)[256 + tid] = pbL1;
        }
        {
            float4 v = *(const float4*)&Agg[arow][kc + akp];
            uint32_t h0, l0, h1, l1;
            split2(v.x, v.y, h0, l0);
            split2(v.z, v.w, h1, l1);
            Ahu[acol] = h0; Ahu[acol + 1] = h1;
            Alu[acol] = l0; Alu[acol + 1] = l1;
        }
        __syncthreads();
        if (c < 7) {
            int nk = kc + 16;
            const uint4* s4h = (const uint4*)(g_B2h + nk * B2U);
            const uint4* s4l = (const uint4*)(g_B2l + nk * B2U);
            pbH0 = s4h[tid]; pbL0 = s4l[tid];
            if (tid < BCH4 - 256) { pbH1 = s4h[256 + tid]; pbL1 = s4l[256 + tid]; }
        }

        uint32_t ah0, ah1, ah2, ah3, al0, al1, al2, al3;
        LDSM_X4(ah0, ah1, ah2, ah3, aAddrH);
        LDSM_X4(al0, al1, al2, al3, aAddrL);

        #pragma unroll
        for (int p = 0; p < 4; p++) {
            uint32_t bh0, bh1, bh2, bh3, bl0, bl1, bl2, bl3;
            LDSM_X4_T(bh0, bh1, bh2, bh3, bAddrH + p * 32);
            LDSM_X4_T(bl0, bl1, bl2, bl3, bAddrL + p * 32);
            MMA16816(acc[2*p],   ah0, ah1, ah2, ah3, bh0, bh1);
            MMA16816(acc[2*p],   ah0, ah1, ah2, ah3, bl0, bl1);
            MMA16816(acc[2*p],   al0, al1, al2, al3, bh0, bh1);
            MMA16816(acc[2*p+1], ah0, ah1, ah2, ah3, bh2, bh3);
            MMA16816(acc[2*p+1], ah0, ah1, ah2, ah3, bl2, bl3);
            MMA16816(acc[2*p+1], al0, al1, al2, al3, bh2, bh3);
        }
        __syncthreads();
    }

    // -------- epilogue: z1 | r1 --------
    #pragma unroll
    for (int nt = 0; nt < 8; nt++) {
        int col = col0 + nt * 8;
        float* dst = (col < 64) ? g_z1 : g_r1;
        int cc = col & 63;
        if (gm0 < M) {
            float2 o; o.x = acc[nt][0]; o.y = acc[nt][1];
            *(float2*)&dst[gm0 * 64 + cc] = o;
        }
        if (gm1 < M) {
            float2 o; o.x = acc[nt][2]; o.y = acc[nt][3];
            *(float2*)&dst[gm1 * 64 + cc] = o;
        }
    }
}

// ---------------- final: out = mean_agg(z1) + bl1 + r1 ---------------------
__global__ void k_out(const float* __restrict__ bias, float* __restrict__ out, int n) {
    int warp = (blockIdx.x * blockDim.x + threadIdx.x) >> 5;
    int lane = threadIdx.x & 31;
    if (warp >= n) return;
    int rs = g_rptr[warp], re = g_rptr[warp + 1];
    int d0 = lane * 2;
    float2 acc = make_float2(0.f, 0.f);
    int j = rs;
    for (; j + 4 <= re; j += 4) {
        int s0 = g_col[j], s1 = g_col[j + 1], s2 = g_col[j + 2], s3 = g_col[j + 3];
        float2 v0 = *(const float2*)&g_z1[s0 * 64 + d0];
        float2 v1 = *(const float2*)&g_z1[s1 * 64 + d0];
        float2 v2 = *(const float2*)&g_z1[s2 * 64 + d0];
        float2 v3 = *(const float2*)&g_z1[s3 * 64 + d0];
        acc.x += v0.x + v1.x + v2.x + v3.x;
        acc.y += v0.y + v1.y + v2.y + v3.y;
    }
    for (; j < re; j++) {
        int s = g_col[j];
        float2 v = *(const float2*)&g_z1[s * 64 + d0];
        acc.x += v.x; acc.y += v.y;
    }
    int deg = re - rs;
    float inv = 1.0f / (float)(deg > 1 ? deg : 1);
    float2 r = *(const float2*)&g_r1[warp * 64 + d0];
    float2 o;
    o.x = acc.x * inv + bias[d0]     + r.x;
    o.y = acc.y * inv + bias[d0 + 1] + r.y;
    *(float2*)&out[warp * 64 + d0] = o;
}

// ---------------- launch (kernel launches ONLY) ----------------------------
extern "C" void kernel_launch(void* const* d_in, const int* in_sizes, int n_in,
                              void* d_out, int out_size) {
    const float* x   = (const float*)d_in[0];
    const void*  ei  = d_in[1];
    const float* Wl0 = (const float*)d_in[2];
    const float* bl0 = (const float*)d_in[3];
    const float* Wr0 = (const float*)d_in[4];
    const float* Wl1 = (const float*)d_in[5];
    const float* bl1 = (const float*)d_in[6];
    const float* Wr1 = (const float*)d_in[7];
    float* out = (float*)d_out;

    int M = in_sizes[0] / 128;      // 100000
    int E = in_sizes[1] / 2;        // 1600000

    k_zero<<<(M + 255) / 256, 256>>>((const int*)ei, M);
    k_hist<<<(E + 255) / 256, 256>>>(ei, E);
    k_scan_blocks<<<NB, SCAN_B>>>(M);
    k_add_off<<<NB, SCAN_B>>>(M, E, NB);
    k_scatter<<<(E + 255) / 256, 256>>>(ei, E);
    k_pack<<<(256 * B1U + 255) / 256, 256>>>(Wl0, Wr0, Wl1, Wr1);

    int tiles = (M + 63) / 64;
    k_layer1<<<tiles, 256>>>(x, bl0, M);
    k_out<<<(M + 7) / 8, 256>>>(bl1, out, M);
}